// round 1
// baseline (speedup 1.0000x reference)
#include <cuda_runtime.h>

#define NSs   5000
#define NMm   100000
#define NRr   2000
#define HH    128
#define ESM   2000000
#define ERM   1000000
#define ESIM  2000000
#define LL    500000

#define CDIV(a,b) (((a)+(b)-1)/(b))

// ---------------- device scratch (no allocations allowed) ----------------
static __device__ float g_XS[2][NSs*HH];
static __device__ float g_XM[2][NMm*HH];
static __device__ float g_XR[2][NRr*HH];
static __device__ float g_SCR[NMm*HH];

static __device__ int g_adj0[ESM];   // sm edges grouped by dst_sm (mrna), val=src_sm
static __device__ int g_adj1[ESM];   // sm edges grouped by src_sm (srna), val=dst_sm
static __device__ int g_adj2[ERM];   // rm by dst_rm (mrna), val=src_rm
static __device__ int g_adj3[ERM];   // rm by src_rm (rbp),  val=dst_rm
static __device__ int g_adj4[ESIM];  // sim by dst_sim, val=src_sim (gcn fwd)
static __device__ int g_adj5[ESIM];  // sim by src_sim, val=dst_sim (gcn rev)

static __device__ int g_off0[NMm+1];
static __device__ int g_off1[NSs+1];
static __device__ int g_off2[NMm+1];
static __device__ int g_off3[NRr+1];
static __device__ int g_off4[NMm+1];
static __device__ int g_off5[NMm+1];

static __device__ int g_cnt[NMm];
static __device__ int g_incl[NMm];
static __device__ int g_cur[NMm];
static __device__ int g_bsums[1024];

static __device__ float g_dinvF[NMm];
static __device__ float g_dinvR[NMm];
static __device__ float g_Wsum[HH*HH];

// ---------------- small utility kernels ----------------
__global__ void k_zero_i(int* p, int n){
    int i = blockIdx.x*blockDim.x + threadIdx.x;
    if (i < n) p[i] = 0;
}
__global__ void k_copy_i(const int* __restrict__ a, int* __restrict__ b, int n){
    int i = blockIdx.x*blockDim.x + threadIdx.x;
    if (i < n) b[i] = a[i];
}
__global__ void k_count(const int* __restrict__ key, int e, int* cnt){
    int i = blockIdx.x*blockDim.x + threadIdx.x;
    if (i < e) atomicAdd(&cnt[key[i]], 1);
}
// inclusive scan pass 1 (1024 elems / block)
__global__ void k_scan1(const int* __restrict__ in, int n, int* __restrict__ incl, int* __restrict__ bsums){
    __shared__ int sh[1024];
    int i = blockIdx.x*1024 + threadIdx.x;
    sh[threadIdx.x] = (i < n) ? in[i] : 0;
    __syncthreads();
    for (int d = 1; d < 1024; d <<= 1){
        int t = (threadIdx.x >= d) ? sh[threadIdx.x - d] : 0;
        __syncthreads();
        sh[threadIdx.x] += t;
        __syncthreads();
    }
    if (i < n) incl[i] = sh[threadIdx.x];
    if (threadIdx.x == 1023) bsums[blockIdx.x] = sh[1023];
}
__global__ void k_scan2(int* bsums, int nb){
    __shared__ int sh[1024];
    sh[threadIdx.x] = (threadIdx.x < nb) ? bsums[threadIdx.x] : 0;
    __syncthreads();
    for (int d = 1; d < 1024; d <<= 1){
        int t = (threadIdx.x >= d) ? sh[threadIdx.x - d] : 0;
        __syncthreads();
        sh[threadIdx.x] += t;
        __syncthreads();
    }
    if (threadIdx.x < nb) bsums[threadIdx.x] = sh[threadIdx.x];
}
__global__ void k_scan3(const int* __restrict__ incl, const int* __restrict__ bsums, int n, int* __restrict__ off){
    int i = blockIdx.x*1024 + threadIdx.x;
    if (i < n){
        int add = blockIdx.x ? bsums[blockIdx.x - 1] : 0;
        off[i+1] = incl[i] + add;
        if (i == 0) off[0] = 0;
    }
}
__global__ void k_fill(const int* __restrict__ key, const int* __restrict__ val, int e,
                       int* cur, int* __restrict__ adj){
    int i = blockIdx.x*blockDim.x + threadIdx.x;
    if (i < e){
        int p = atomicAdd(&cur[key[i]], 1);
        adj[p] = val[i];
    }
}
__global__ void k_dinv(const int* __restrict__ off, int n, float* __restrict__ dinv){
    int i = blockIdx.x*blockDim.x + threadIdx.x;
    if (i < n) dinv[i] = rsqrtf((float)(off[i+1] - off[i] + 1));
}
__global__ void k_addmat(const float* __restrict__ a, const float* __restrict__ b, float* __restrict__ c, int n){
    int i = blockIdx.x*blockDim.x + threadIdx.x;
    if (i < n) c[i] = a[i] + b[i];
}
__global__ void k_relu(float* __restrict__ x, int n4){
    int i = blockIdx.x*blockDim.x + threadIdx.x;
    if (i < n4){
        float4 v = ((float4*)x)[i];
        v.x = fmaxf(v.x, 0.f); v.y = fmaxf(v.y, 0.f);
        v.z = fmaxf(v.z, 0.f); v.w = fmaxf(v.w, 0.f);
        ((float4*)x)[i] = v;
    }
}

// ---------------- aggregation kernels: one warp per destination node ----------------
__global__ void k_agg_mean(const float* __restrict__ X, const int* __restrict__ adj,
                           const int* __restrict__ off, int n, float* __restrict__ out){
    int w = (blockIdx.x*blockDim.x + threadIdx.x) >> 5;
    int lane = threadIdx.x & 31;
    if (w >= n) return;
    int beg = off[w], end = off[w+1];
    int c = lane * 4;
    float4 acc = make_float4(0.f, 0.f, 0.f, 0.f);
    int j = beg;
    for (; j + 4 <= end; j += 4){
        int n0 = adj[j], n1 = adj[j+1], n2 = adj[j+2], n3 = adj[j+3];
        float4 v0 = *(const float4*)(X + (size_t)n0*HH + c);
        float4 v1 = *(const float4*)(X + (size_t)n1*HH + c);
        float4 v2 = *(const float4*)(X + (size_t)n2*HH + c);
        float4 v3 = *(const float4*)(X + (size_t)n3*HH + c);
        acc.x += v0.x + v1.x + v2.x + v3.x;
        acc.y += v0.y + v1.y + v2.y + v3.y;
        acc.z += v0.z + v1.z + v2.z + v3.z;
        acc.w += v0.w + v1.w + v2.w + v3.w;
    }
    for (; j < end; j++){
        int nb = adj[j];
        float4 v = *(const float4*)(X + (size_t)nb*HH + c);
        acc.x += v.x; acc.y += v.y; acc.z += v.z; acc.w += v.w;
    }
    int cnt = end - beg;
    float inv = 1.f / (float)(cnt > 1 ? cnt : 1);
    float4 r = make_float4(acc.x*inv, acc.y*inv, acc.z*inv, acc.w*inv);
    *(float4*)(out + (size_t)w*HH + c) = r;
}

__global__ void k_agg_gcn(const float* __restrict__ X, const int* __restrict__ adj,
                          const int* __restrict__ off, const float* __restrict__ dinv,
                          int n, float* __restrict__ out){
    int w = (blockIdx.x*blockDim.x + threadIdx.x) >> 5;
    int lane = threadIdx.x & 31;
    if (w >= n) return;
    int beg = off[w], end = off[w+1];
    int c = lane * 4;
    float wd = dinv[w];
    // self loop: dinv[d]^2 * x[d]
    float4 xx = *(const float4*)(X + (size_t)w*HH + c);
    float ws = wd * wd;
    float4 acc = make_float4(ws*xx.x, ws*xx.y, ws*xx.z, ws*xx.w);
    int j = beg;
    for (; j + 4 <= end; j += 4){
        int n0 = adj[j], n1 = adj[j+1], n2 = adj[j+2], n3 = adj[j+3];
        float w0 = wd * dinv[n0], w1 = wd * dinv[n1], w2 = wd * dinv[n2], w3 = wd * dinv[n3];
        float4 v0 = *(const float4*)(X + (size_t)n0*HH + c);
        float4 v1 = *(const float4*)(X + (size_t)n1*HH + c);
        float4 v2 = *(const float4*)(X + (size_t)n2*HH + c);
        float4 v3 = *(const float4*)(X + (size_t)n3*HH + c);
        acc.x += w0*v0.x + w1*v1.x + w2*v2.x + w3*v3.x;
        acc.y += w0*v0.y + w1*v1.y + w2*v2.y + w3*v3.y;
        acc.z += w0*v0.z + w1*v1.z + w2*v2.z + w3*v3.z;
        acc.w += w0*v0.w + w1*v1.w + w2*v2.w + w3*v3.w;
    }
    for (; j < end; j++){
        int nb = adj[j];
        float wn = wd * dinv[nb];
        float4 v = *(const float4*)(X + (size_t)nb*HH + c);
        acc.x += wn*v.x; acc.y += wn*v.y; acc.z += wn*v.z; acc.w += wn*v.w;
    }
    *(float4*)(out + (size_t)w*HH + c) = acc;
}

// ---------------- GEMM: C[n,128] (+)= A[n,128] @ W[128,128] (+ bias) ----------------
// 128x128 tile per block, 256 threads, 8x8 register tile per thread.
__global__ void __launch_bounds__(256, 2)
k_gemm(const float* __restrict__ A, const float* __restrict__ W,
       const float* __restrict__ bias, float* __restrict__ C, int n, int accFlag){
    __shared__ float As[8][132];   // padded to avoid store bank conflicts
    __shared__ float Ws[8][128];
    const int t = threadIdx.x;
    const int row0 = blockIdx.x * 128;
    const int ty = t >> 4, tx = t & 15;
    const int r0 = ty * 8, c0 = tx * 8;
    const int lrow = t >> 1;
    const int lk4  = (t & 1) * 4;
    const int wkk  = t >> 5;
    const int wcol = (t & 31) * 4;

    float accv[8][8];
    #pragma unroll
    for (int i = 0; i < 8; i++)
        #pragma unroll
        for (int j = 0; j < 8; j++) accv[i][j] = 0.f;

    for (int k0 = 0; k0 < 128; k0 += 8){
        float4 av = make_float4(0.f, 0.f, 0.f, 0.f);
        int gr = row0 + lrow;
        if (gr < n) av = *(const float4*)(A + (size_t)gr*HH + k0 + lk4);
        As[lk4+0][lrow] = av.x; As[lk4+1][lrow] = av.y;
        As[lk4+2][lrow] = av.z; As[lk4+3][lrow] = av.w;
        *(float4*)&Ws[wkk][wcol] = *(const float4*)(W + (size_t)(k0+wkk)*HH + wcol);
        __syncthreads();
        #pragma unroll
        for (int kk = 0; kk < 8; kk++){
            float4 a0 = *(const float4*)&As[kk][r0];
            float4 a1 = *(const float4*)&As[kk][r0+4];
            float4 b0 = *(const float4*)&Ws[kk][c0];
            float4 b1 = *(const float4*)&Ws[kk][c0+4];
            float aa[8] = {a0.x,a0.y,a0.z,a0.w,a1.x,a1.y,a1.z,a1.w};
            float bb[8] = {b0.x,b0.y,b0.z,b0.w,b1.x,b1.y,b1.z,b1.w};
            #pragma unroll
            for (int i = 0; i < 8; i++)
                #pragma unroll
                for (int j = 0; j < 8; j++)
                    accv[i][j] = fmaf(aa[i], bb[j], accv[i][j]);
        }
        __syncthreads();
    }

    float bv[8];
    if (bias){
        float4 b0 = *(const float4*)(bias + c0);
        float4 b1 = *(const float4*)(bias + c0 + 4);
        bv[0]=b0.x; bv[1]=b0.y; bv[2]=b0.z; bv[3]=b0.w;
        bv[4]=b1.x; bv[5]=b1.y; bv[6]=b1.z; bv[7]=b1.w;
    } else {
        #pragma unroll
        for (int j = 0; j < 8; j++) bv[j] = 0.f;
    }

    #pragma unroll
    for (int i = 0; i < 8; i++){
        int gr = row0 + r0 + i;
        if (gr >= n) continue;
        float* cp = C + (size_t)gr*HH + c0;
        float o[8];
        #pragma unroll
        for (int j = 0; j < 8; j++) o[j] = accv[i][j] + bv[j];
        if (accFlag){
            float4 c0v = *(const float4*)cp;
            float4 c1v = *(const float4*)(cp + 4);
            o[0]+=c0v.x; o[1]+=c0v.y; o[2]+=c0v.z; o[3]+=c0v.w;
            o[4]+=c1v.x; o[5]+=c1v.y; o[6]+=c1v.z; o[7]+=c1v.w;
        }
        *(float4*)cp       = make_float4(o[0],o[1],o[2],o[3]);
        *(float4*)(cp + 4) = make_float4(o[4],o[5],o[6],o[7]);
    }
}

// ---------------- prediction readout: warp per dot product ----------------
__global__ void k_pred(const float* __restrict__ XS, const float* __restrict__ XM,
                       const float* __restrict__ XR,
                       const int* __restrict__ ls, const int* __restrict__ lm,
                       const int* __restrict__ lr, float* __restrict__ out){
    int w = (blockIdx.x*blockDim.x + threadIdx.x) >> 5;
    int lane = threadIdx.x & 31;
    if (w >= 2*LL) return;
    const float *a, *b;
    if (w < LL){
        a = XS + (size_t)ls[w]*HH;
        b = XM + (size_t)lm[w]*HH;
    } else {
        int j = w - LL;
        a = XR + (size_t)lr[j]*HH;
        b = XM + (size_t)lm[j]*HH;
    }
    float4 u = *(const float4*)(a + lane*4);
    float4 v = *(const float4*)(b + lane*4);
    float s = u.x*v.x + u.y*v.y + u.z*v.z + u.w*v.w;
    #pragma unroll
    for (int d = 16; d; d >>= 1) s += __shfl_xor_sync(0xffffffffu, s, d);
    if (lane == 0) out[w] = s;
}

// ---------------- host orchestration ----------------
static void build_csr(const int* key, const int* val, int e, int n,
                      int* adj, int* off, int* cnt, int* incl, int* cur, int* bsums){
    k_zero_i<<<CDIV(n,256),256>>>(cnt, n);
    k_count<<<CDIV(e,256),256>>>(key, e, cnt);
    int nb = CDIV(n, 1024);
    k_scan1<<<nb,1024>>>(cnt, n, incl, bsums);
    k_scan2<<<1,1024>>>(bsums, nb);
    k_scan3<<<nb,1024>>>(incl, bsums, n, off);
    k_copy_i<<<CDIV(n,256),256>>>(off, cur, n);
    k_fill<<<CDIV(e,256),256>>>(key, val, e, cur, adj);
}

static inline void* symaddr(const void* sym){
    void* p = nullptr;
    cudaGetSymbolAddress(&p, sym);
    return p;
}

extern "C" void kernel_launch(void* const* d_in, const int* in_sizes, int n_in,
                              void* d_out, int out_size){
    const float* emb_s  = (const float*)d_in[0];
    const float* emb_m  = (const float*)d_in[1];
    const float* emb_r  = (const float*)d_in[2];
    const float* sageWl = (const float*)d_in[3];   // [2,4,H,H]
    const float* sageBl = (const float*)d_in[4];   // [2,4,H]
    const float* sageWr = (const float*)d_in[5];   // [2,4,H,H]
    const float* gcnW   = (const float*)d_in[6];   // [2,2,H,H]
    const float* gcnB   = (const float*)d_in[7];   // [2,2,H]
    const int* src_sm   = (const int*)d_in[8];
    const int* dst_sm   = (const int*)d_in[9];
    const int* src_rm   = (const int*)d_in[10];
    const int* dst_rm   = (const int*)d_in[11];
    const int* src_sim  = (const int*)d_in[12];
    const int* dst_sim  = (const int*)d_in[13];
    const int* lbl_s    = (const int*)d_in[14];
    const int* lbl_m    = (const int*)d_in[15];
    const int* lbl_r    = (const int*)d_in[16];
    float* out = (float*)d_out;

    float* XS   = (float*)symaddr(g_XS);
    float* XM   = (float*)symaddr(g_XM);
    float* XR   = (float*)symaddr(g_XR);
    float* SCR  = (float*)symaddr(g_SCR);
    int* adj0 = (int*)symaddr(g_adj0);
    int* adj1 = (int*)symaddr(g_adj1);
    int* adj2 = (int*)symaddr(g_adj2);
    int* adj3 = (int*)symaddr(g_adj3);
    int* adj4 = (int*)symaddr(g_adj4);
    int* adj5 = (int*)symaddr(g_adj5);
    int* off0 = (int*)symaddr(g_off0);
    int* off1 = (int*)symaddr(g_off1);
    int* off2 = (int*)symaddr(g_off2);
    int* off3 = (int*)symaddr(g_off3);
    int* off4 = (int*)symaddr(g_off4);
    int* off5 = (int*)symaddr(g_off5);
    int* cnt  = (int*)symaddr(g_cnt);
    int* incl = (int*)symaddr(g_incl);
    int* cur  = (int*)symaddr(g_cur);
    int* bsum = (int*)symaddr(g_bsums);
    float* dinvF = (float*)symaddr(g_dinvF);
    float* dinvR = (float*)symaddr(g_dinvR);
    float* Wsum  = (float*)symaddr(g_Wsum);

    // ---- CSR builds (graph fixed per call; reused by both layers) ----
    build_csr(dst_sm,  src_sm,  ESM,  NMm, adj0, off0, cnt, incl, cur, bsum);
    build_csr(src_sm,  dst_sm,  ESM,  NSs, adj1, off1, cnt, incl, cur, bsum);
    build_csr(dst_rm,  src_rm,  ERM,  NMm, adj2, off2, cnt, incl, cur, bsum);
    build_csr(src_rm,  dst_rm,  ERM,  NRr, adj3, off3, cnt, incl, cur, bsum);
    build_csr(dst_sim, src_sim, ESIM, NMm, adj4, off4, cnt, incl, cur, bsum);
    build_csr(src_sim, dst_sim, ESIM, NMm, adj5, off5, cnt, incl, cur, bsum);

    k_dinv<<<CDIV(NMm,256),256>>>(off4, NMm, dinvF);
    k_dinv<<<CDIV(NMm,256),256>>>(off5, NMm, dinvR);

    const int HW = HH*HH;

    for (int l = 0; l < 2; l++){
        const float* xs = l ? (XS + 0*(size_t)NSs*HH) : emb_s;
        const float* xm = l ? (XM + 0*(size_t)NMm*HH) : emb_m;
        const float* xr = l ? (XR + 0*(size_t)NRr*HH) : emb_r;
        float* XSo = XS + (size_t)l*NSs*HH;
        float* XMo = XM + (size_t)l*NMm*HH;
        float* XRo = XR + (size_t)l*NRr*HH;

        const float* Wl0 = sageWl + (size_t)(l*4+0)*HW;
        const float* Wl1 = sageWl + (size_t)(l*4+1)*HW;
        const float* Wl2 = sageWl + (size_t)(l*4+2)*HW;
        const float* Wl3 = sageWl + (size_t)(l*4+3)*HW;
        const float* bl0 = sageBl + (size_t)(l*4+0)*HH;
        const float* bl1 = sageBl + (size_t)(l*4+1)*HH;
        const float* bl2 = sageBl + (size_t)(l*4+2)*HH;
        const float* bl3 = sageBl + (size_t)(l*4+3)*HH;
        const float* Wr0 = sageWr + (size_t)(l*4+0)*HW;
        const float* Wr1 = sageWr + (size_t)(l*4+1)*HW;
        const float* Wr2 = sageWr + (size_t)(l*4+2)*HW;
        const float* Wr3 = sageWr + (size_t)(l*4+3)*HW;
        const float* gW0 = gcnW + (size_t)(l*2+0)*HW;
        const float* gW1 = gcnW + (size_t)(l*2+1)*HW;
        const float* gb0 = gcnB + (size_t)(l*2+0)*HH;
        const float* gb1 = gcnB + (size_t)(l*2+1)*HH;

        // ---- m target ----
        k_addmat<<<CDIV(HW,256),256>>>(Wr0, Wr2, Wsum, HW);

        k_agg_mean<<<CDIV(NMm,8),256>>>(xs, adj0, off0, NMm, SCR);
        k_gemm<<<CDIV(NMm,128),256>>>(SCR, Wl0, bl0, XMo, NMm, 0);

        k_agg_mean<<<CDIV(NMm,8),256>>>(xr, adj2, off2, NMm, SCR);
        k_gemm<<<CDIV(NMm,128),256>>>(SCR, Wl2, bl2, XMo, NMm, 1);

        k_gemm<<<CDIV(NMm,128),256>>>(xm, Wsum, nullptr, XMo, NMm, 1);

        k_agg_gcn<<<CDIV(NMm,8),256>>>(xm, adj4, off4, dinvF, NMm, SCR);
        k_gemm<<<CDIV(NMm,128),256>>>(SCR, gW0, gb0, XMo, NMm, 1);

        k_agg_gcn<<<CDIV(NMm,8),256>>>(xm, adj5, off5, dinvR, NMm, SCR);
        k_gemm<<<CDIV(NMm,128),256>>>(SCR, gW1, gb1, XMo, NMm, 1);

        // ---- s target ----
        k_agg_mean<<<CDIV(NSs,8),256>>>(xm, adj1, off1, NSs, SCR);
        k_gemm<<<CDIV(NSs,128),256>>>(SCR, Wl1, bl1, XSo, NSs, 0);
        k_gemm<<<CDIV(NSs,128),256>>>(xs, Wr1, nullptr, XSo, NSs, 1);

        // ---- r target ----
        k_agg_mean<<<CDIV(NRr,8),256>>>(xm, adj3, off3, NRr, SCR);
        k_gemm<<<CDIV(NRr,128),256>>>(SCR, Wl3, bl3, XRo, NRr, 0);
        k_gemm<<<CDIV(NRr,128),256>>>(xr, Wr3, nullptr, XRo, NRr, 1);

        // ---- relu ----
        k_relu<<<CDIV(NMm*HH/4,256),256>>>(XMo, NMm*HH/4);
        k_relu<<<CDIV(NSs*HH/4,256),256>>>(XSo, NSs*HH/4);
        k_relu<<<CDIV(NRr*HH/4,256),256>>>(XRo, NRr*HH/4);
    }

    // ---- readout ----
    const float* XSf = XS + (size_t)1*NSs*HH;
    const float* XMf = XM + (size_t)1*NMm*HH;
    const float* XRf = XR + (size_t)1*NRr*HH;
    k_pred<<<CDIV(2*LL,8),256>>>(XSf, XMf, XRf, lbl_s, lbl_m, lbl_r, out);

    (void)in_sizes; (void)n_in; (void)out_size;
}

// round 4
// speedup vs baseline: 1.5030x; 1.5030x over previous
#include <cuda_runtime.h>
#include <cuda_bf16.h>
#include <cstdint>

#define NSs   5000
#define NMm   100000
#define NRr   2000
#define HH    128
#define ESM   2000000
#define ERM   1000000
#define ESIM  2000000
#define LL    500000
#define KTM   640      // fused K for mrna target
#define KT2   256      // fused K for srna/rbp targets

#define CDIV(a,b) (((a)+(b)-1)/(b))

// ---------------- device scratch ----------------
static __device__ float g_XS[2][NSs*HH];
static __device__ float g_XM[2][NMm*HH];
static __device__ float g_XR[2][NRr*HH];

static __device__ __nv_bfloat16 g_Amh[(size_t)NMm*KTM];
static __device__ __nv_bfloat16 g_Aml[(size_t)NMm*KTM];
static __device__ __nv_bfloat16 g_Ash[(size_t)NSs*KT2];
static __device__ __nv_bfloat16 g_Asl[(size_t)NSs*KT2];
static __device__ __nv_bfloat16 g_Arh[(size_t)NRr*KT2];
static __device__ __nv_bfloat16 g_Arl[(size_t)NRr*KT2];

static __device__ __nv_bfloat16 g_Bmh[HH*KTM], g_Bml[HH*KTM];
static __device__ __nv_bfloat16 g_Bsh[HH*KT2], g_Bsl[HH*KT2];
static __device__ __nv_bfloat16 g_Brh[HH*KT2], g_Brl[HH*KT2];
static __device__ float g_biasM[HH];

static __device__ int g_adj0[ESM];
static __device__ int g_adj1[ESM];
static __device__ int g_adj2[ERM];
static __device__ int g_adj3[ERM];
static __device__ int g_adj4[ESIM];
static __device__ int g_adj5[ESIM];

static __device__ int g_off0[NMm+1];
static __device__ int g_off1[NSs+1];
static __device__ int g_off2[NMm+1];
static __device__ int g_off3[NRr+1];
static __device__ int g_off4[NMm+1];
static __device__ int g_off5[NMm+1];

static __device__ int g_cnt[NMm];
static __device__ int g_incl[NMm];
static __device__ int g_cur[NMm];
static __device__ int g_bsums[1024];

static __device__ float g_dinvF[NMm];
static __device__ float g_dinvR[NMm];

// ---------------- bf16 hi/lo split helper ----------------
__device__ __forceinline__ void split_store4(float a, float b, float c, float d,
                                             __nv_bfloat16* oh, __nv_bfloat16* ol){
    __nv_bfloat16 ha = __float2bfloat16(a), hb = __float2bfloat16(b),
                  hc = __float2bfloat16(c), hd = __float2bfloat16(d);
    __nv_bfloat16 la = __float2bfloat16(a - __bfloat162float(ha));
    __nv_bfloat16 lb = __float2bfloat16(b - __bfloat162float(hb));
    __nv_bfloat16 lc = __float2bfloat16(c - __bfloat162float(hc));
    __nv_bfloat16 ld = __float2bfloat16(d - __bfloat162float(hd));
    ushort4 H; H.x = __bfloat16_as_ushort(ha); H.y = __bfloat16_as_ushort(hb);
               H.z = __bfloat16_as_ushort(hc); H.w = __bfloat16_as_ushort(hd);
    ushort4 L; L.x = __bfloat16_as_ushort(la); L.y = __bfloat16_as_ushort(lb);
               L.z = __bfloat16_as_ushort(lc); L.w = __bfloat16_as_ushort(ld);
    *(ushort4*)oh = H;
    *(ushort4*)ol = L;
}

// ---------------- CSR build utilities ----------------
__global__ void k_zero_i(int* p, int n){
    int i = blockIdx.x*blockDim.x + threadIdx.x;
    if (i < n) p[i] = 0;
}
__global__ void k_copy_i(const int* __restrict__ a, int* __restrict__ b, int n){
    int i = blockIdx.x*blockDim.x + threadIdx.x;
    if (i < n) b[i] = a[i];
}
__global__ void k_count(const int* __restrict__ key, int e, int* cnt){
    int i = blockIdx.x*blockDim.x + threadIdx.x;
    if (i < e) atomicAdd(&cnt[key[i]], 1);
}
__global__ void k_scan1(const int* __restrict__ in, int n, int* __restrict__ incl, int* __restrict__ bsums){
    __shared__ int sh[1024];
    int i = blockIdx.x*1024 + threadIdx.x;
    sh[threadIdx.x] = (i < n) ? in[i] : 0;
    __syncthreads();
    for (int d = 1; d < 1024; d <<= 1){
        int t = (threadIdx.x >= d) ? sh[threadIdx.x - d] : 0;
        __syncthreads();
        sh[threadIdx.x] += t;
        __syncthreads();
    }
    if (i < n) incl[i] = sh[threadIdx.x];
    if (threadIdx.x == 1023) bsums[blockIdx.x] = sh[1023];
}
__global__ void k_scan2(int* bsums, int nb){
    __shared__ int sh[1024];
    sh[threadIdx.x] = (threadIdx.x < nb) ? bsums[threadIdx.x] : 0;
    __syncthreads();
    for (int d = 1; d < 1024; d <<= 1){
        int t = (threadIdx.x >= d) ? sh[threadIdx.x - d] : 0;
        __syncthreads();
        sh[threadIdx.x] += t;
        __syncthreads();
    }
    if (threadIdx.x < nb) bsums[threadIdx.x] = sh[threadIdx.x];
}
__global__ void k_scan3(const int* __restrict__ incl, const int* __restrict__ bsums, int n, int* __restrict__ off){
    int i = blockIdx.x*1024 + threadIdx.x;
    if (i < n){
        int add = blockIdx.x ? bsums[blockIdx.x - 1] : 0;
        off[i+1] = incl[i] + add;
        if (i == 0) off[0] = 0;
    }
}
__global__ void k_fill(const int* __restrict__ key, const int* __restrict__ val, int e,
                       int* cur, int* __restrict__ adj){
    int i = blockIdx.x*blockDim.x + threadIdx.x;
    if (i < e){
        int p = atomicAdd(&cur[key[i]], 1);
        adj[p] = val[i];
    }
}
__global__ void k_dinv(const int* __restrict__ off, int n, float* __restrict__ dinv){
    int i = blockIdx.x*blockDim.x + threadIdx.x;
    if (i < n) dinv[i] = rsqrtf((float)(off[i+1] - off[i] + 1));
}

// ---------------- weight-stack / bias builders ----------------
__global__ void k_buildB_m(const float* __restrict__ Wl0, const float* __restrict__ Wl2,
                           const float* __restrict__ Wr0, const float* __restrict__ Wr2,
                           const float* __restrict__ gW0, const float* __restrict__ gW1,
                           __nv_bfloat16* __restrict__ oh, __nv_bfloat16* __restrict__ ol){
    int i = blockIdx.x*blockDim.x + threadIdx.x;
    if (i >= HH*KTM) return;
    int n = i / KTM, k = i % KTM;
    int sl = k >> 7, kk = k & 127;
    float v;
    if      (sl == 0) v = Wl0[kk*HH + n];
    else if (sl == 1) v = Wl2[kk*HH + n];
    else if (sl == 2) v = Wr0[kk*HH + n] + Wr2[kk*HH + n];
    else if (sl == 3) v = gW0[kk*HH + n];
    else              v = gW1[kk*HH + n];
    __nv_bfloat16 h = __float2bfloat16(v);
    oh[i] = h;
    ol[i] = __float2bfloat16(v - __bfloat162float(h));
}
__global__ void k_buildB_2(const float* __restrict__ Wa, const float* __restrict__ Wb,
                           __nv_bfloat16* __restrict__ oh, __nv_bfloat16* __restrict__ ol){
    int i = blockIdx.x*blockDim.x + threadIdx.x;
    if (i >= HH*KT2) return;
    int n = i / KT2, k = i % KT2;
    float v = (k < 128) ? Wa[(k&127)*HH + n] : Wb[(k&127)*HH + n];
    __nv_bfloat16 h = __float2bfloat16(v);
    oh[i] = h;
    ol[i] = __float2bfloat16(v - __bfloat162float(h));
}
__global__ void k_bias4(const float* a, const float* b, const float* c, const float* d, float* o){
    int i = threadIdx.x;
    if (i < HH) o[i] = a[i] + b[i] + c[i] + d[i];
}

// ---------------- aggregation: warp per dst, writes bf16 hi/lo slice ----------------
__global__ void k_agg_mean(const float* __restrict__ X, const int* __restrict__ adj,
                           const int* __restrict__ off, int n,
                           __nv_bfloat16* __restrict__ oh, __nv_bfloat16* __restrict__ ol,
                           int Kt, int coloff){
    int w = (blockIdx.x*blockDim.x + threadIdx.x) >> 5;
    int lane = threadIdx.x & 31;
    if (w >= n) return;
    int beg = off[w], end = off[w+1];
    int c = lane * 4;
    float4 acc = make_float4(0.f, 0.f, 0.f, 0.f);
    int j = beg;
    for (; j + 4 <= end; j += 4){
        int n0 = adj[j], n1 = adj[j+1], n2 = adj[j+2], n3 = adj[j+3];
        float4 v0 = *(const float4*)(X + (size_t)n0*HH + c);
        float4 v1 = *(const float4*)(X + (size_t)n1*HH + c);
        float4 v2 = *(const float4*)(X + (size_t)n2*HH + c);
        float4 v3 = *(const float4*)(X + (size_t)n3*HH + c);
        acc.x += v0.x + v1.x + v2.x + v3.x;
        acc.y += v0.y + v1.y + v2.y + v3.y;
        acc.z += v0.z + v1.z + v2.z + v3.z;
        acc.w += v0.w + v1.w + v2.w + v3.w;
    }
    for (; j < end; j++){
        int nb = adj[j];
        float4 v = *(const float4*)(X + (size_t)nb*HH + c);
        acc.x += v.x; acc.y += v.y; acc.z += v.z; acc.w += v.w;
    }
    int cnt = end - beg;
    float inv = 1.f / (float)(cnt > 1 ? cnt : 1);
    size_t base = (size_t)w*Kt + coloff + c;
    split_store4(acc.x*inv, acc.y*inv, acc.z*inv, acc.w*inv, oh + base, ol + base);
}

__global__ void k_agg_gcn(const float* __restrict__ X, const int* __restrict__ adj,
                          const int* __restrict__ off, const float* __restrict__ dinv,
                          int n, __nv_bfloat16* __restrict__ oh, __nv_bfloat16* __restrict__ ol,
                          int Kt, int coloff){
    int w = (blockIdx.x*blockDim.x + threadIdx.x) >> 5;
    int lane = threadIdx.x & 31;
    if (w >= n) return;
    int beg = off[w], end = off[w+1];
    int c = lane * 4;
    float wd = dinv[w];
    float4 xx = *(const float4*)(X + (size_t)w*HH + c);
    float ws = wd * wd;
    float4 acc = make_float4(ws*xx.x, ws*xx.y, ws*xx.z, ws*xx.w);
    int j = beg;
    for (; j + 4 <= end; j += 4){
        int n0 = adj[j], n1 = adj[j+1], n2 = adj[j+2], n3 = adj[j+3];
        float w0 = wd * dinv[n0], w1 = wd * dinv[n1], w2 = wd * dinv[n2], w3 = wd * dinv[n3];
        float4 v0 = *(const float4*)(X + (size_t)n0*HH + c);
        float4 v1 = *(const float4*)(X + (size_t)n1*HH + c);
        float4 v2 = *(const float4*)(X + (size_t)n2*HH + c);
        float4 v3 = *(const float4*)(X + (size_t)n3*HH + c);
        acc.x += w0*v0.x + w1*v1.x + w2*v2.x + w3*v3.x;
        acc.y += w0*v0.y + w1*v1.y + w2*v2.y + w3*v3.y;
        acc.z += w0*v0.z + w1*v1.z + w2*v2.z + w3*v3.z;
        acc.w += w0*v0.w + w1*v1.w + w2*v2.w + w3*v3.w;
    }
    for (; j < end; j++){
        int nb = adj[j];
        float wn = wd * dinv[nb];
        float4 v = *(const float4*)(X + (size_t)nb*HH + c);
        acc.x += wn*v.x; acc.y += wn*v.y; acc.z += wn*v.z; acc.w += wn*v.w;
    }
    size_t base = (size_t)w*Kt + coloff + c;
    split_store4(acc.x, acc.y, acc.z, acc.w, oh + base, ol + base);
}

__global__ void k_root(const float* __restrict__ X,
                       __nv_bfloat16* __restrict__ oh, __nv_bfloat16* __restrict__ ol,
                       int n, int Kt, int coloff){
    int idx = blockIdx.x*blockDim.x + threadIdx.x;
    if (idx >= n*32) return;
    int w = idx >> 5, c4 = (idx & 31) * 4;
    float4 v = *(const float4*)(X + (size_t)w*HH + c4);
    size_t base = (size_t)w*Kt + coloff + c4;
    split_store4(v.x, v.y, v.z, v.w, oh + base, ol + base);
}

// ---------------- HMMA GEMM: X[n,128] = relu(A[n,Kt] @ B^T + bias) ----------------
// mma.sync m16n8k16 bf16. A: [n,Kt] hi/lo, B: [128,Kt] hi/lo (row=output col, k contiguous).
// CTA 256 thr / 8 warps; C tile 128x128; warp tile 64x32.
#define LDSB 72                       // smem row stride in bf16 (144B, conflict-free)
#define SM_BUF (128*LDSB)             // bf16 elems per buffer
#define SMEM_MMA_BYTES (4*SM_BUF*2)   // 73728

__device__ __forceinline__ void mma_bf16(float* c, const uint32_t* a, const uint32_t* b){
    asm volatile(
        "mma.sync.aligned.m16n8k16.row.col.f32.bf16.bf16.f32 "
        "{%0,%1,%2,%3}, {%4,%5,%6,%7}, {%8,%9}, {%0,%1,%2,%3};"
        : "+f"(c[0]), "+f"(c[1]), "+f"(c[2]), "+f"(c[3])
        : "r"(a[0]), "r"(a[1]), "r"(a[2]), "r"(a[3]), "r"(b[0]), "r"(b[1]));
}

__global__ void __launch_bounds__(256)
k_mma(const __nv_bfloat16* __restrict__ Ah, const __nv_bfloat16* __restrict__ Al,
      const __nv_bfloat16* __restrict__ Bh, const __nv_bfloat16* __restrict__ Bl,
      const float* __restrict__ bias, float* __restrict__ Xout, int n, int Ktot)
{
    extern __shared__ __nv_bfloat16 sm[];
    __nv_bfloat16* sAh = sm;
    __nv_bfloat16* sAl = sm + SM_BUF;
    __nv_bfloat16* sBh = sm + 2*SM_BUF;
    __nv_bfloat16* sBl = sm + 3*SM_BUF;

    const int tid  = threadIdx.x;
    const int wid  = tid >> 5;
    const int lane = tid & 31;
    const int g    = lane >> 2;       // group id (0-7)
    const int t2   = lane & 3;        // thread in group
    const int warp_m = wid & 1;       // 2 warp-rows of 64
    const int warp_n = wid >> 1;      // 4 warp-cols of 32
    const int row0 = blockIdx.x * 128;

    float acc[4][4][4];
    #pragma unroll
    for (int mt = 0; mt < 4; mt++)
        #pragma unroll
        for (int nt = 0; nt < 4; nt++)
            #pragma unroll
            for (int r = 0; r < 4; r++) acc[mt][nt][r] = 0.f;

    for (int kc = 0; kc < Ktot; kc += 64){
        // ---- stage chunk into smem: 4 buffers x 128 rows x 64 bf16 ----
        #pragma unroll
        for (int j = 0; j < 4; j++){
            int idx = tid + j*256;          // uint4 index (8 bf16)
            int row = idx >> 3, c8 = idx & 7;
            uint4 va = make_uint4(0,0,0,0), vb = va;
            int gr = row0 + row;
            if (gr < n){
                va = *(const uint4*)(Ah + (size_t)gr*Ktot + kc + c8*8);
                vb = *(const uint4*)(Al + (size_t)gr*Ktot + kc + c8*8);
            }
            *(uint4*)(sAh + row*LDSB + c8*8) = va;
            *(uint4*)(sAl + row*LDSB + c8*8) = vb;
            *(uint4*)(sBh + row*LDSB + c8*8) = *(const uint4*)(Bh + (size_t)row*Ktot + kc + c8*8);
            *(uint4*)(sBl + row*LDSB + c8*8) = *(const uint4*)(Bl + (size_t)row*Ktot + kc + c8*8);
        }
        __syncthreads();

        // ---- compute: 4 k16 steps ----
        #pragma unroll
        for (int ks = 0; ks < 4; ks++){
            const int k0 = ks * 16;
            uint32_t afh[4][4], afl[4][4], bfh[4][2], bfl[4][2];
            #pragma unroll
            for (int mt = 0; mt < 4; mt++){
                int rbase = warp_m*64 + mt*16;
                #pragma unroll
                for (int r = 0; r < 4; r++){
                    int row = rbase + g + (r & 1)*8;
                    int col = k0 + t2*2 + (r >> 1)*8;
                    afh[mt][r] = *(const uint32_t*)(sAh + row*LDSB + col);
                    afl[mt][r] = *(const uint32_t*)(sAl + row*LDSB + col);
                }
            }
            #pragma unroll
            for (int nt = 0; nt < 4; nt++){
                int nrow = warp_n*32 + nt*8 + g;
                #pragma unroll
                for (int r = 0; r < 2; r++){
                    int col = k0 + t2*2 + r*8;
                    bfh[nt][r] = *(const uint32_t*)(sBh + nrow*LDSB + col);
                    bfl[nt][r] = *(const uint32_t*)(sBl + nrow*LDSB + col);
                }
            }
            #pragma unroll
            for (int mt = 0; mt < 4; mt++)
                #pragma unroll
                for (int nt = 0; nt < 4; nt++){
                    mma_bf16(acc[mt][nt], afh[mt], bfh[nt]);
                    mma_bf16(acc[mt][nt], afh[mt], bfl[nt]);
                    mma_bf16(acc[mt][nt], afl[mt], bfh[nt]);
                }
        }
        __syncthreads();
    }

    // ---- epilogue: bias + relu + store ----
    #pragma unroll
    for (int mt = 0; mt < 4; mt++){
        #pragma unroll
        for (int nt = 0; nt < 4; nt++){
            int col = warp_n*32 + nt*8 + t2*2;
            float b0 = bias[col], b1 = bias[col+1];
            int r0 = row0 + warp_m*64 + mt*16 + g;
            if (r0 < n){
                float2 o;
                o.x = fmaxf(acc[mt][nt][0] + b0, 0.f);
                o.y = fmaxf(acc[mt][nt][1] + b1, 0.f);
                *(float2*)(Xout + (size_t)r0*HH + col) = o;
            }
            int r1 = r0 + 8;
            if (r1 < n){
                float2 o;
                o.x = fmaxf(acc[mt][nt][2] + b0, 0.f);
                o.y = fmaxf(acc[mt][nt][3] + b1, 0.f);
                *(float2*)(Xout + (size_t)r1*HH + col) = o;
            }
        }
    }
}

// ---------------- readout ----------------
__global__ void k_pred(const float* __restrict__ XS, const float* __restrict__ XM,
                       const float* __restrict__ XR,
                       const int* __restrict__ ls, const int* __restrict__ lm,
                       const int* __restrict__ lr, float* __restrict__ out){
    int w = (blockIdx.x*blockDim.x + threadIdx.x) >> 5;
    int lane = threadIdx.x & 31;
    if (w >= 2*LL) return;
    const float *a, *b;
    if (w < LL){
        a = XS + (size_t)ls[w]*HH;
        b = XM + (size_t)lm[w]*HH;
    } else {
        int j = w - LL;
        a = XR + (size_t)lr[j]*HH;
        b = XM + (size_t)lm[j]*HH;
    }
    float4 u = *(const float4*)(a + lane*4);
    float4 v = *(const float4*)(b + lane*4);
    float s = u.x*v.x + u.y*v.y + u.z*v.z + u.w*v.w;
    #pragma unroll
    for (int d = 16; d; d >>= 1) s += __shfl_xor_sync(0xffffffffu, s, d);
    if (lane == 0) out[w] = s;
}

// ---------------- host ----------------
static void build_csr(const int* key, const int* val, int e, int n,
                      int* adj, int* off, int* cnt, int* incl, int* cur, int* bsums){
    k_zero_i<<<CDIV(n,256),256>>>(cnt, n);
    k_count<<<CDIV(e,256),256>>>(key, e, cnt);
    int nb = CDIV(n, 1024);
    k_scan1<<<nb,1024>>>(cnt, n, incl, bsums);
    k_scan2<<<1,1024>>>(bsums, nb);
    k_scan3<<<nb,1024>>>(incl, bsums, n, off);
    k_copy_i<<<CDIV(n,256),256>>>(off, cur, n);
    k_fill<<<CDIV(e,256),256>>>(key, val, e, cur, adj);
}

static inline void* symaddr(const void* sym){
    void* p = nullptr;
    cudaGetSymbolAddress(&p, sym);
    return p;
}

extern "C" void kernel_launch(void* const* d_in, const int* in_sizes, int n_in,
                              void* d_out, int out_size){
    const float* emb_s  = (const float*)d_in[0];
    const float* emb_m  = (const float*)d_in[1];
    const float* emb_r  = (const float*)d_in[2];
    const float* sageWl = (const float*)d_in[3];
    const float* sageBl = (const float*)d_in[4];
    const float* sageWr = (const float*)d_in[5];
    const float* gcnW   = (const float*)d_in[6];
    const float* gcnB   = (const float*)d_in[7];
    const int* src_sm   = (const int*)d_in[8];
    const int* dst_sm   = (const int*)d_in[9];
    const int* src_rm   = (const int*)d_in[10];
    const int* dst_rm   = (const int*)d_in[11];
    const int* src_sim  = (const int*)d_in[12];
    const int* dst_sim  = (const int*)d_in[13];
    const int* lbl_s    = (const int*)d_in[14];
    const int* lbl_m    = (const int*)d_in[15];
    const int* lbl_r    = (const int*)d_in[16];
    float* out = (float*)d_out;

    cudaFuncSetAttribute(k_mma, cudaFuncAttributeMaxDynamicSharedMemorySize, SMEM_MMA_BYTES);

    float* XS = (float*)symaddr(g_XS);
    float* XM = (float*)symaddr(g_XM);
    float* XR = (float*)symaddr(g_XR);
    __nv_bfloat16* Amh = (__nv_bfloat16*)symaddr(g_Amh);
    __nv_bfloat16* Aml = (__nv_bfloat16*)symaddr(g_Aml);
    __nv_bfloat16* Ash = (__nv_bfloat16*)symaddr(g_Ash);
    __nv_bfloat16* Asl = (__nv_bfloat16*)symaddr(g_Asl);
    __nv_bfloat16* Arh = (__nv_bfloat16*)symaddr(g_Arh);
    __nv_bfloat16* Arl = (__nv_bfloat16*)symaddr(g_Arl);
    __nv_bfloat16* Bmh = (__nv_bfloat16*)symaddr(g_Bmh);
    __nv_bfloat16* Bml = (__nv_bfloat16*)symaddr(g_Bml);
    __nv_bfloat16* Bsh = (__nv_bfloat16*)symaddr(g_Bsh);
    __nv_bfloat16* Bsl = (__nv_bfloat16*)symaddr(g_Bsl);
    __nv_bfloat16* Brh = (__nv_bfloat16*)symaddr(g_Brh);
    __nv_bfloat16* Brl = (__nv_bfloat16*)symaddr(g_Brl);
    float* biasM = (float*)symaddr(g_biasM);
    int* adj0 = (int*)symaddr(g_adj0);
    int* adj1 = (int*)symaddr(g_adj1);
    int* adj2 = (int*)symaddr(g_adj2);
    int* adj3 = (int*)symaddr(g_adj3);
    int* adj4 = (int*)symaddr(g_adj4);
    int* adj5 = (int*)symaddr(g_adj5);
    int* off0 = (int*)symaddr(g_off0);
    int* off1 = (int*)symaddr(g_off1);
    int* off2 = (int*)symaddr(g_off2);
    int* off3 = (int*)symaddr(g_off3);
    int* off4 = (int*)symaddr(g_off4);
    int* off5 = (int*)symaddr(g_off5);
    int* cnt  = (int*)symaddr(g_cnt);
    int* incl = (int*)symaddr(g_incl);
    int* cur  = (int*)symaddr(g_cur);
    int* bsum = (int*)symaddr(g_bsums);
    float* dinvF = (float*)symaddr(g_dinvF);
    float* dinvR = (float*)symaddr(g_dinvR);

    build_csr(dst_sm,  src_sm,  ESM,  NMm, adj0, off0, cnt, incl, cur, bsum);
    build_csr(src_sm,  dst_sm,  ESM,  NSs, adj1, off1, cnt, incl, cur, bsum);
    build_csr(dst_rm,  src_rm,  ERM,  NMm, adj2, off2, cnt, incl, cur, bsum);
    build_csr(src_rm,  dst_rm,  ERM,  NRr, adj3, off3, cnt, incl, cur, bsum);
    build_csr(dst_sim, src_sim, ESIM, NMm, adj4, off4, cnt, incl, cur, bsum);
    build_csr(src_sim, dst_sim, ESIM, NMm, adj5, off5, cnt, incl, cur, bsum);

    k_dinv<<<CDIV(NMm,256),256>>>(off4, NMm, dinvF);
    k_dinv<<<CDIV(NMm,256),256>>>(off5, NMm, dinvR);

    const int HW = HH*HH;

    for (int l = 0; l < 2; l++){
        const float* xs = l ? XS : emb_s;
        const float* xm = l ? XM : emb_m;
        const float* xr = l ? XR : emb_r;
        float* XSo = XS + (size_t)l*NSs*HH;
        float* XMo = XM + (size_t)l*NMm*HH;
        float* XRo = XR + (size_t)l*NRr*HH;

        const float* Wl0 = sageWl + (size_t)(l*4+0)*HW;
        const float* Wl1 = sageWl + (size_t)(l*4+1)*HW;
        const float* Wl2 = sageWl + (size_t)(l*4+2)*HW;
        const float* Wl3 = sageWl + (size_t)(l*4+3)*HW;
        const float* bl0 = sageBl + (size_t)(l*4+0)*HH;
        const float* bl1 = sageBl + (size_t)(l*4+1)*HH;
        const float* bl2 = sageBl + (size_t)(l*4+2)*HH;
        const float* bl3 = sageBl + (size_t)(l*4+3)*HH;
        const float* Wr0 = sageWr + (size_t)(l*4+0)*HW;
        const float* Wr1 = sageWr + (size_t)(l*4+1)*HW;
        const float* Wr2 = sageWr + (size_t)(l*4+2)*HW;
        const float* Wr3 = sageWr + (size_t)(l*4+3)*HW;
        const float* gW0 = gcnW + (size_t)(l*2+0)*HW;
        const float* gW1 = gcnW + (size_t)(l*2+1)*HW;
        const float* gb0 = gcnB + (size_t)(l*2+0)*HH;
        const float* gb1 = gcnB + (size_t)(l*2+1)*HH;

        // weight stacks + fused bias
        k_buildB_m<<<CDIV(HH*KTM,256),256>>>(Wl0, Wl2, Wr0, Wr2, gW0, gW1, Bmh, Bml);
        k_buildB_2<<<CDIV(HH*KT2,256),256>>>(Wl1, Wr1, Bsh, Bsl);
        k_buildB_2<<<CDIV(HH*KT2,256),256>>>(Wl3, Wr3, Brh, Brl);
        k_bias4<<<1,128>>>(bl0, bl2, gb0, gb1, biasM);

        // m-target A slices: [mean_s | mean_r | root | gcn_fwd | gcn_rev]
        k_agg_mean<<<CDIV(NMm,8),256>>>(xs, adj0, off0, NMm, Amh, Aml, KTM, 0);
        k_agg_mean<<<CDIV(NMm,8),256>>>(xr, adj2, off2, NMm, Amh, Aml, KTM, 128);
        k_root<<<CDIV(NMm*32,256),256>>>(xm, Amh, Aml, NMm, KTM, 256);
        k_agg_gcn<<<CDIV(NMm,8),256>>>(xm, adj4, off4, dinvF, NMm, Amh, Aml, KTM, 384);
        k_agg_gcn<<<CDIV(NMm,8),256>>>(xm, adj5, off5, dinvR, NMm, Amh, Aml, KTM, 512);
        // s-target: [mean from m | root]
        k_agg_mean<<<CDIV(NSs,8),256>>>(xm, adj1, off1, NSs, Ash, Asl, KT2, 0);
        k_root<<<CDIV(NSs*32,256),256>>>(xs, Ash, Asl, NSs, KT2, 128);
        // r-target
        k_agg_mean<<<CDIV(NRr,8),256>>>(xm, adj3, off3, NRr, Arh, Arl, KT2, 0);
        k_root<<<CDIV(NRr*32,256),256>>>(xr, Arh, Arl, NRr, KT2, 128);

        // fused HMMA GEMMs (bias+relu fused)
        k_mma<<<CDIV(NMm,128),256,SMEM_MMA_BYTES>>>(Amh, Aml, Bmh, Bml, biasM, XMo, NMm, KTM);
        k_mma<<<CDIV(NSs,128),256,SMEM_MMA_BYTES>>>(Ash, Asl, Bsh, Bsl, bl1, XSo, NSs, KT2);
        k_mma<<<CDIV(NRr,128),256,SMEM_MMA_BYTES>>>(Arh, Arl, Brh, Brl, bl3, XRo, NRr, KT2);
    }

    const float* XSf = XS + (size_t)1*NSs*HH;
    const float* XMf = XM + (size_t)1*NMm*HH;
    const float* XRf = XR + (size_t)1*NRr*HH;
    k_pred<<<CDIV(2*LL,8),256>>>(XSf, XMf, XRf, lbl_s, lbl_m, lbl_r, out);

    (void)in_sizes; (void)n_in; (void)out_size;
}